// round 2
// baseline (speedup 1.0000x reference)
#include <cuda_runtime.h>

// LIF neuron: x is (N*T, F), row b = n*T + t, T=4, N=64, F=65536.
// Per (n,f): v=0; 4x { v = v*0.5 + x_t; s=(v>=1); v-=s; } out=s.
// Streaming problem. R2: 2 float4 per thread -> MLP=8 front-batched loads,
// shift/mask indexing (no 64-bit div).

#define T_STEPS 4
#define DECAY 0.5f
#define VTH 1.0f

#define FVEC 16384          // F/4
#define F4_PER_BLOCK 512    // 256 threads x 2 float4
#define BLOCKS_PER_N 32     // FVEC / F4_PER_BLOCK  (power of two)

__global__ void __launch_bounds__(256) lif_kernel(const float4* __restrict__ x,
                                                  float4* __restrict__ out)
{
    // blockIdx.x = n * BLOCKS_PER_N + c
    int n = blockIdx.x >> 5;           // / BLOCKS_PER_N
    int c = blockIdx.x & 31;           // % BLOCKS_PER_N

    int f4a = c * F4_PER_BLOCK + threadIdx.x;        // first column
    int f4b = f4a + 256;                             // second column

    long long rowbase = (long long)n * T_STEPS * FVEC;
    long long a = rowbase + f4a;
    long long b = rowbase + f4b;

    // Front-batch all 8 loads (MLP_p1 = 8).
    float4 xa0 = x[a];
    float4 xa1 = x[a + FVEC];
    float4 xa2 = x[a + 2 * FVEC];
    float4 xa3 = x[a + 3 * FVEC];
    float4 xb0 = x[b];
    float4 xb1 = x[b + FVEC];
    float4 xb2 = x[b + 2 * FVEC];
    float4 xb3 = x[b + 3 * FVEC];

    float4 va = make_float4(0.f, 0.f, 0.f, 0.f);
    float4 vb = make_float4(0.f, 0.f, 0.f, 0.f);
    float4 sa0, sa1, sa2, sa3, sb0, sb1, sb2, sb3;

#define STEP1(v, xt, st)                                                  \
    (v) = (v) * DECAY + (xt); (st) = ((v) >= VTH) ? 1.f : 0.f; (v) -= (st) * VTH;
#define STEP4(v, xt, st)            \
    STEP1(v.x, (xt).x, (st).x)      \
    STEP1(v.y, (xt).y, (st).y)      \
    STEP1(v.z, (xt).z, (st).z)      \
    STEP1(v.w, (xt).w, (st).w)

    STEP4(va, xa0, sa0)
    STEP4(va, xa1, sa1)
    STEP4(va, xa2, sa2)
    STEP4(va, xa3, sa3)
    STEP4(vb, xb0, sb0)
    STEP4(vb, xb1, sb1)
    STEP4(vb, xb2, sb2)
    STEP4(vb, xb3, sb3)
#undef STEP4
#undef STEP1

    out[a]            = sa0;
    out[b]            = sb0;
    out[a + FVEC]     = sa1;
    out[b + FVEC]     = sb1;
    out[a + 2 * FVEC] = sa2;
    out[b + 2 * FVEC] = sb2;
    out[a + 3 * FVEC] = sa3;
    out[b + 3 * FVEC] = sb3;
}

extern "C" void kernel_launch(void* const* d_in, const int* in_sizes, int n_in,
                              void* d_out, int out_size)
{
    const float* x = (const float*)d_in[0];
    float* out = (float*)d_out;

    const int N = 64;                      // 256 rows / T=4
    int blocks = N * BLOCKS_PER_N;         // 2048 blocks x 256 threads

    lif_kernel<<<blocks, 256>>>((const float4*)x, (float4*)out);
}

// round 3
// speedup vs baseline: 1.0779x; 1.0779x over previous
#include <cuda_runtime.h>

// LIF neuron: x is (N*T, F), row b = n*T + t, T=4, N=64, F=65536.
// Per (n,f): v=0; 4x { v = v*0.5 + x_t; s=(v>=1); v-=s; } out=s.
// R3: at HBM roofline (7.6 TB/s measured). Streaming cache hints (.cs) on
// both load & store (no reuse, working set > L2), pure 32-bit indexing.

#define T_STEPS 4
#define DECAY 0.5f
#define VTH 1.0f

#define FVEC 16384          // F/4
#define BLOCKS_PER_N 64     // FVEC / 256 threads

__global__ void __launch_bounds__(256) lif_kernel(const float4* __restrict__ x,
                                                  float4* __restrict__ out)
{
    // blockIdx.x = n * BLOCKS_PER_N + c ; power-of-two split, all 32-bit.
    unsigned n = blockIdx.x >> 6;              // / 64
    unsigned c = blockIdx.x & 63;              // % 64

    unsigned base = n * (T_STEPS * FVEC) + c * 256u + threadIdx.x;  // max ~4.19M, fits u32

    // Front-batch 4 streaming loads (evict-first: no reuse, don't pollute L2).
    float4 x0 = __ldcs(&x[base]);
    float4 x1 = __ldcs(&x[base + FVEC]);
    float4 x2 = __ldcs(&x[base + 2 * FVEC]);
    float4 x3 = __ldcs(&x[base + 3 * FVEC]);

    float4 v = make_float4(0.f, 0.f, 0.f, 0.f);
    float4 s0, s1, s2, s3;

#define STEP1(vc, xt, st)                                                  \
    (vc) = (vc) * DECAY + (xt); (st) = ((vc) >= VTH) ? 1.f : 0.f; (vc) -= (st) * VTH;
#define STEP4(xt, st)            \
    STEP1(v.x, (xt).x, (st).x)   \
    STEP1(v.y, (xt).y, (st).y)   \
    STEP1(v.z, (xt).z, (st).z)   \
    STEP1(v.w, (xt).w, (st).w)

    STEP4(x0, s0)
    STEP4(x1, s1)
    STEP4(x2, s2)
    STEP4(x3, s3)
#undef STEP4
#undef STEP1

    __stcs(&out[base],            s0);
    __stcs(&out[base + FVEC],     s1);
    __stcs(&out[base + 2 * FVEC], s2);
    __stcs(&out[base + 3 * FVEC], s3);
}

extern "C" void kernel_launch(void* const* d_in, const int* in_sizes, int n_in,
                              void* d_out, int out_size)
{
    const float* x = (const float*)d_in[0];
    float* out = (float*)d_out;

    const int N = 64;                       // 256 rows / T=4
    int blocks = N * BLOCKS_PER_N;          // 4096 blocks x 256 threads

    lif_kernel<<<blocks, 256>>>((const float4*)x, (float4*)out);
}